// round 15
// baseline (speedup 1.0000x reference)
#include <cuda_runtime.h>
#include <cuda_bf16.h>
#include <cstdint>

#define B_ 1024
#define T_ 200

typedef unsigned long long ull;
typedef unsigned int uint32;

// Scratch for x-projections: [3][rid=b*T+t][128] fp32 (static device global).
// Layout is rid-major so proj's writes are dense/streaming (rid consecutive
// within a tile -> 512B-apart lines), unlike the old [m][t][B][j] layout
// whose consecutive-t writes were 512KB apart.
__device__ float g_proj[(size_t)3 * T_ * B_ * 128];

// HW tanh (MUFU.TANH, sm_75+; base PTX feature).
__device__ __forceinline__ float tanh_hw(float x) {
    float t; asm("tanh.approx.f32 %0, %1;" : "=f"(t) : "f"(x)); return t;
}
__device__ __forceinline__ float sig_hw(float x) {
    return 0.5f * tanh_hw(0.5f * x) + 0.5f;
}

__device__ __forceinline__ uint32 pk_bf16(float a, float b) {
    return (uint32)__bfloat16_as_ushort(__float2bfloat16(a)) |
           ((uint32)__bfloat16_as_ushort(__float2bfloat16(b)) << 16);
}
__device__ __forceinline__ float bf16hi_res(float v, float& hi) {
    __nv_bfloat16 h = __float2bfloat16(v);
    hi = __bfloat162float(h);
    return v - hi;
}
__device__ __forceinline__ void mma_bf16(float& c0, float& c1, float& c2, float& c3,
                                         uint32 a0, uint32 a1, uint32 a2, uint32 a3,
                                         uint32 b0, uint32 b1) {
    asm volatile(
        "mma.sync.aligned.m16n8k16.row.col.f32.bf16.bf16.f32 "
        "{%0,%1,%2,%3}, {%4,%5,%6,%7}, {%8,%9}, {%0,%1,%2,%3};"
        : "+f"(c0), "+f"(c1), "+f"(c2), "+f"(c3)
        : "r"(a0), "r"(a1), "r"(a2), "r"(a3), "r"(b0), "r"(b1));
}

// ---------------------------------------------------------------------------
// Pass 1 (HMMA): g_proj[m][rid][:] = X[rid][:] @ Wm_top, bf16-split, 256 thr.
// Fragment-packed smem (as round 14); epilogue now writes rid-major (dense).
// ---------------------------------------------------------------------------
__global__ __launch_bounds__(256, 1) void proj_kernel(
    const float* __restrict__ x,
    const float* __restrict__ Wu, const float* __restrict__ Wr,
    const float* __restrict__ Wc)
{
    extern __shared__ char smc[];
    char* fB  = smc;                     // [48 g][8 kt][32 lane][16B]
    char* fAh = smc + 196608;            // [2 rt][8 kt][32 lane][16B]
    char* fAl = smc + 204800;
    const int tid  = threadIdx.x;
    const int w    = tid >> 5;
    const int lane = tid & 31;
    const int gr   = lane >> 2;
    const int gc   = lane & 3;
    const int wr   = w >> 2;            // row-group 0..1
    const int wc   = w & 3;             // col-group 0..3 (12 n-tiles each)

    // ---- build fragB from W (top halves), coalesced over j ----
    {
        const float* Ws[3] = {Wu, Wr, Wc};
        for (int idx = tid; idx < 24576; idx += 256) {
            int j  = idx & 127;
            int kp = (idx >> 7) & 63;      // k pair index, k = 2*kp
            int m  = idx >> 13;
            int k  = kp * 2;
            const float* W = Ws[m];
            float h0, h1;
            float l0 = bf16hi_res(W[k * 128 + j], h0);
            float l1 = bf16hi_res(W[(k + 1) * 128 + j], h1);
            int g   = m * 16 + (j >> 3);
            int grr = j & 7;
            int kt  = k >> 4;
            int qcc = (k & 7) >> 1;
            int hi8 = (k & 8) >> 3;        // 0: b0 slot, 1: b1 slot
            char* cell = fB + (((g * 8 + kt) * 32 + grr * 4 + qcc) << 4);
            *(uint32*)(cell + hi8 * 4)     = pk_bf16(h0, h1);   // bh0/bh1
            *(uint32*)(cell + 8 + hi8 * 4) = pk_bf16(l0, l1);   // bl0/bl1
        }
    }

    const float4* x4 = (const float4*)x;
    const int ntiles = (B_ * T_) / 32;     // 6400

    float4 xreg[4];
    int tile = blockIdx.x;
    if (tile < ntiles) {
#pragma unroll
        for (int c = 0; c < 4; ++c) xreg[c] = x4[(size_t)tile * 1024 + tid + c * 256];
    }

    for (; tile < ntiles; tile += gridDim.x) {
        __syncthreads();   // previous tile's readers done (covers fragB init)
        // ---- stage X into A-fragment layout ----
#pragma unroll
        for (int c = 0; c < 4; ++c) {
            int f = tid + c * 256;
            int r = f >> 5;                // 0..31
            int k0 = (f & 31) * 4;
            float4 v = xreg[c];
            int rt = r >> 4, rr = r & 15;
            int grr = rr & 7;
            int rowslot = rr >> 3;         // 0 -> a0/a2, 1 -> a1/a3
#pragma unroll
            for (int p_ = 0; p_ < 2; ++p_) {
                int kk = k0 + 2 * p_;
                float e = (p_ == 0) ? v.x : v.z;
                float o = (p_ == 0) ? v.y : v.w;
                int kt  = kk >> 4;
                int qcc = (kk & 7) >> 1;
                int fld = rowslot + (((kk & 8) >> 3) << 1);   // 0..3
                uint32 off = (((rt * 8 + kt) * 32 + grr * 4 + qcc) << 4) + fld * 4;
                float hhe, hho;
                float le = bf16hi_res(e, hhe);
                float lo_ = bf16hi_res(o, hho);
                *(uint32*)(fAh + off) = pk_bf16(hhe, hho);
                *(uint32*)(fAl + off) = pk_bf16(le, lo_);
            }
        }
        __syncthreads();   // fragA ready

        int ntile = tile + gridDim.x;
        if (ntile < ntiles) {
#pragma unroll
            for (int c = 0; c < 4; ++c) xreg[c] = x4[(size_t)ntile * 1024 + tid + c * 256];
        }

        float C[12][4];
#pragma unroll
        for (int n = 0; n < 12; ++n)
#pragma unroll
            for (int i = 0; i < 4; ++i) C[n][i] = 0.f;

#pragma unroll
        for (int kt = 0; kt < 8; ++kt) {
            const uint32 aoff = ((wr * 8 + kt) * 32 + lane) << 4;
            uint4 Ah = *(const uint4*)(fAh + aoff);
            uint4 Al = *(const uint4*)(fAl + aoff);
#pragma unroll
            for (int nt = 0; nt < 12; ++nt) {
                int g = wc * 12 + nt;
                uint4 Bf = *(const uint4*)(fB + (((g * 8 + kt) * 32 + lane) << 4));
                mma_bf16(C[nt][0], C[nt][1], C[nt][2], C[nt][3],
                         Ah.x, Ah.y, Ah.z, Ah.w, Bf.x, Bf.y);
                mma_bf16(C[nt][0], C[nt][1], C[nt][2], C[nt][3],
                         Ah.x, Ah.y, Ah.z, Ah.w, Bf.z, Bf.w);
                mma_bf16(C[nt][0], C[nt][1], C[nt][2], C[nt][3],
                         Al.x, Al.y, Al.z, Al.w, Bf.x, Bf.y);
            }
        }

        // ---- epilogue: rid-major writes (dense, streaming) ----
        const int ridA = tile * 32 + wr * 16 + gr;
        const int ridB = ridA + 8;
#pragma unroll
        for (int nt = 0; nt < 12; ++nt) {
            int cgl = wc * 96 + nt * 8 + gc * 2;
            int m = cgl >> 7, j = cgl & 127;
            float* dA = g_proj + ((size_t)m * (B_ * T_) + ridA) * 128 + j;
            float* dB = g_proj + ((size_t)m * (B_ * T_) + ridB) * 128 + j;
            *(float2*)dA = make_float2(C[nt][0], C[nt][1]);
            *(float2*)dB = make_float2(C[nt][2], C[nt][3]);
        }
    }
}

// ---------------------------------------------------------------------------
// Pass 2 (HMMA recurrence): round-12 structure (known 382-391us).
// Only change: g_proj read indexing for the rid-major layout.
// ---------------------------------------------------------------------------
__global__ __launch_bounds__(256, 1) void rec_kernel(
    const float* __restrict__ att,
    const void* __restrict__ slen_raw,
    const float* __restrict__ Wu, const float* __restrict__ Wr,
    const float* __restrict__ Wc,
    float* __restrict__ out)
{
    extern __shared__ char smr[];
    uint32* hfrag = (uint32*)smr;             // [8 kt][32 lane][4 u32]  4096 B
    uint32* sfrag = (uint32*)(smr + 4096);    // [8 kt][32 lane][4 u32]  4096 B
    uint32* blo   = (uint32*)(smr + 8192);    // [48 g][8 kt][32 lane][2 u32] 98304 B
    __shared__ int s_is64;

    const int tid  = threadIdx.x;
    const int w    = tid >> 5;
    const int lane = tid & 31;
    const int qr   = lane >> 2;
    const int qc   = lane & 3;
    const int row  = blockIdx.x * 8 + qr;
    const int colA = w * 16 + qc * 2;
    const int colB = colA + 8;

    uint32 bhi[6][8][2];
#pragma unroll
    for (int f = 0; f < 6; ++f) {
        const float* Wsrc = (f < 2) ? Wu : (f < 4 ? Wr : Wc);
        const int n = w * 16 + (f & 1) * 8 + qr;
#pragma unroll
        for (int kt = 0; kt < 8; ++kt) {
            int k = kt * 16 + qc * 2;
            float h00, h01, h10, h11;
            float l00 = bf16hi_res(Wsrc[16384 + k * 128 + n], h00);
            float l01 = bf16hi_res(Wsrc[16384 + (k + 1) * 128 + n], h01);
            float l10 = bf16hi_res(Wsrc[16384 + (k + 8) * 128 + n], h10);
            float l11 = bf16hi_res(Wsrc[16384 + (k + 9) * 128 + n], h11);
            bhi[f][kt][0] = pk_bf16(h00, h01);
            bhi[f][kt][1] = pk_bf16(h10, h11);
            uint32* dst = blo + (((w * 6 + f) * 8 + kt) * 32 + lane) * 2;
            dst[0] = pk_bf16(l00, l01);
            dst[1] = pk_bf16(l10, l11);
        }
    }
    for (int i = tid; i < 1024; i += 256) hfrag[i] = 0u;
    if (tid == 0) {
        const int* a = (const int*)slen_raw;
        s_is64 = (a[1] == 0 && a[3] == 0 && a[5] == 0 && a[7] == 0) ? 1 : 0;
    }
    __syncthreads();

    int sl;
    if (s_is64) sl = (int)((const long long*)slen_raw)[row];
    else        sl = ((const int*)slen_raw)[row];

    float h0 = 0.f, h1 = 0.f, h2 = 0.f, h3 = 0.f;

    for (int t = 0; t < T_; ++t) {
        float Dg[4][4];
#pragma unroll
        for (int f = 0; f < 4; ++f)
#pragma unroll
            for (int i = 0; i < 4; ++i) Dg[f][i] = 0.f;

#pragma unroll
        for (int kt = 0; kt < 8; ++kt) {
            uint4 af = *(const uint4*)(hfrag + (kt * 32 + lane) * 4);
#pragma unroll
            for (int f = 0; f < 4; ++f) {
                const uint32* bl = blo + (((w * 6 + f) * 8 + kt) * 32 + lane) * 2;
                uint32 bl0 = bl[0], bl1 = bl[1];
                mma_bf16(Dg[f][0], Dg[f][1], Dg[f][2], Dg[f][3],
                         af.x, af.z, af.y, af.w, bhi[f][kt][0], bhi[f][kt][1]);
                mma_bf16(Dg[f][0], Dg[f][1], Dg[f][2], Dg[f][3],
                         af.x, af.z, af.y, af.w, bl0, bl1);
            }
        }

        // rid-major g_proj: base = (row*T + t)*128, m stride = B*T*128
        const float* gp = g_proj + ((size_t)row * T_ + t) * 128;
        float2 xuA = *(const float2*)(gp + colA);
        float2 xuB = *(const float2*)(gp + colB);
        float2 xrA = *(const float2*)(gp + (size_t)B_ * T_ * 128 + colA);
        float2 xrB = *(const float2*)(gp + (size_t)B_ * T_ * 128 + colB);
        float uA0 = sig_hw(Dg[0][0] + Dg[0][2] + xuA.x);
        float uA1 = sig_hw(Dg[0][1] + Dg[0][3] + xuA.y);
        float uB0 = sig_hw(Dg[1][0] + Dg[1][2] + xuB.x);
        float uB1 = sig_hw(Dg[1][1] + Dg[1][3] + xuB.y);
        float sA0 = sig_hw(Dg[2][0] + Dg[2][2] + xrA.x) * h0;
        float sA1 = sig_hw(Dg[2][1] + Dg[2][3] + xrA.y) * h1;
        float sB0 = sig_hw(Dg[3][0] + Dg[3][2] + xrB.x) * h2;
        float sB1 = sig_hw(Dg[3][1] + Dg[3][3] + xrB.y) * h3;
        {
            float hA0, hA1, hB0, hB1;
            float lA0 = bf16hi_res(sA0, hA0), lA1 = bf16hi_res(sA1, hA1);
            float lB0 = bf16hi_res(sB0, hB0), lB1 = bf16hi_res(sB1, hB1);
            uint4 sf;
            sf.x = pk_bf16(hA0, hA1); sf.y = pk_bf16(hB0, hB1);
            sf.z = pk_bf16(lA0, lA1); sf.w = pk_bf16(lB0, lB1);
            *(uint4*)(sfrag + (w * 32 + lane) * 4) = sf;
        }
        __syncthreads();

        float Dc[2][4];
#pragma unroll
        for (int f = 0; f < 2; ++f)
#pragma unroll
            for (int i = 0; i < 4; ++i) Dc[f][i] = 0.f;

#pragma unroll
        for (int kt = 0; kt < 8; ++kt) {
            uint4 af = *(const uint4*)(sfrag + (kt * 32 + lane) * 4);
#pragma unroll
            for (int f = 0; f < 2; ++f) {
                const uint32* bl = blo + (((w * 6 + 4 + f) * 8 + kt) * 32 + lane) * 2;
                uint32 bl0 = bl[0], bl1 = bl[1];
                mma_bf16(Dc[f][0], Dc[f][1], Dc[f][2], Dc[f][3],
                         af.x, af.z, af.y, af.w, bhi[4 + f][kt][0], bhi[4 + f][kt][1]);
                mma_bf16(Dc[f][0], Dc[f][1], Dc[f][2], Dc[f][3],
                         af.x, af.z, af.y, af.w, bl0, bl1);
            }
        }

        float2 xcA = *(const float2*)(gp + (size_t)2 * B_ * T_ * 128 + colA);
        float2 xcB = *(const float2*)(gp + (size_t)2 * B_ * T_ * 128 + colB);
        float av = att[(size_t)row * T_ + t];
        bool live = (t < sl);
        {
            float htA0 = tanh_hw(Dc[0][0] + Dc[0][2] + xcA.x);
            float htA1 = tanh_hw(Dc[0][1] + Dc[0][3] + xcA.y);
            float htB0 = tanh_hw(Dc[1][0] + Dc[1][2] + xcB.x);
            float htB1 = tanh_hw(Dc[1][1] + Dc[1][3] + xcB.y);
            float n0 = h0 + uA0 * av * (htA0 - h0);
            float n1 = h1 + uA1 * av * (htA1 - h1);
            float n2 = h2 + uB0 * av * (htB0 - h2);
            float n3 = h3 + uB1 * av * (htB1 - h3);
            h0 = live ? n0 : h0;
            h1 = live ? n1 : h1;
            h2 = live ? n2 : h2;
            h3 = live ? n3 : h3;
        }
        float* op = out + ((size_t)row * T_ + t) * 128;
        *(float2*)(op + colA) = make_float2(h0, h1);
        *(float2*)(op + colB) = make_float2(h2, h3);
        {
            float hA0, hA1, hB0, hB1;
            float lA0 = bf16hi_res(h0, hA0), lA1 = bf16hi_res(h1, hA1);
            float lB0 = bf16hi_res(h2, hB0), lB1 = bf16hi_res(h3, hB1);
            uint4 hf;
            hf.x = pk_bf16(hA0, hA1); hf.y = pk_bf16(hB0, hB1);
            hf.z = pk_bf16(lA0, lA1); hf.w = pk_bf16(lB0, lB1);
            *(uint4*)(hfrag + (w * 32 + lane) * 4) = hf;
        }
        __syncthreads();
    }
}

// ---------------------------------------------------------------------------
extern "C" void kernel_launch(void* const* d_in, const int* in_sizes, int n_in,
                              void* d_out, int out_size)
{
    // Resolve inputs by element count (robust to metadata ordering).
    int iSeq = -1, iLen = -1, iAtt = -1, iW[3] = {-1, -1, -1};
    int nw = 0;
    for (int i = 0; i < n_in; ++i) {
        int s = in_sizes[i];
        if      (s == 26214400) iSeq = i;
        else if (s == 1024)     iLen = i;
        else if (s == 204800)   iAtt = i;
        else if (s == 32768 && nw < 3) iW[nw++] = i;
    }
    if (iSeq < 0 || iLen < 0 || iAtt < 0 || nw != 3) {
        iSeq = 0; iLen = 1; iAtt = 2; iW[0] = 3; iW[1] = 4; iW[2] = 5;
    }
    int iWu, iWr, iWc;
    if (iW[0] < iSeq) { iWc = iW[0]; iWr = iW[1]; iWu = iW[2]; }  // alphabetical
    else              { iWu = iW[0]; iWr = iW[1]; iWc = iW[2]; }  // insertion

    const float* seq_emb = (const float*)d_in[iSeq];
    const void*  slen    = d_in[iLen];
    const float* att     = (const float*)d_in[iAtt];
    const float* Wu      = (const float*)d_in[iWu];
    const float* Wr      = (const float*)d_in[iWr];
    const float* Wc      = (const float*)d_in[iWc];
    float*       out     = (float*)d_out;

    const int smem1 = 196608 + 2 * 8192;      // 212992 B
    const int smem2 = 8192 + 98304;           // 106496 B
    cudaFuncSetAttribute(proj_kernel, cudaFuncAttributeMaxDynamicSharedMemorySize, smem1);
    cudaFuncSetAttribute(rec_kernel,  cudaFuncAttributeMaxDynamicSharedMemorySize, smem2);

    proj_kernel<<<148, 256, smem1>>>(seq_emb, Wu, Wr, Wc);
    rec_kernel<<<128, 256, smem2>>>(att, slen, Wu, Wr, Wc, out);
}

// round 16
// speedup vs baseline: 1.0838x; 1.0838x over previous
#include <cuda_runtime.h>
#include <cuda_bf16.h>
#include <cstdint>

#define B_ 1024
#define T_ 200

typedef unsigned long long ull;
typedef unsigned int uint32;

// Scratch for x-projections: [m][t][B][j] fp32 (rec-friendly layout).
__device__ float g_proj[(size_t)3 * T_ * B_ * 128];

// HW tanh (MUFU.TANH, sm_75+; base PTX feature).
__device__ __forceinline__ float tanh_hw(float x) {
    float t; asm("tanh.approx.f32 %0, %1;" : "=f"(t) : "f"(x)); return t;
}
__device__ __forceinline__ float sig_hw(float x) {
    return 0.5f * tanh_hw(0.5f * x) + 0.5f;
}

__device__ __forceinline__ uint32 pk_bf16(float a, float b) {
    return (uint32)__bfloat16_as_ushort(__float2bfloat16(a)) |
           ((uint32)__bfloat16_as_ushort(__float2bfloat16(b)) << 16);
}
__device__ __forceinline__ float bf16hi_res(float v, float& hi) {
    __nv_bfloat16 h = __float2bfloat16(v);
    hi = __bfloat162float(h);
    return v - hi;
}
__device__ __forceinline__ void mma_bf16(float& c0, float& c1, float& c2, float& c3,
                                         uint32 a0, uint32 a1, uint32 a2, uint32 a3,
                                         uint32 b0, uint32 b1) {
    asm volatile(
        "mma.sync.aligned.m16n8k16.row.col.f32.bf16.bf16.f32 "
        "{%0,%1,%2,%3}, {%4,%5,%6,%7}, {%8,%9}, {%0,%1,%2,%3};"
        : "+f"(c0), "+f"(c1), "+f"(c2), "+f"(c3)
        : "r"(a0), "r"(a1), "r"(a2), "r"(a3), "r"(b0), "r"(b1));
}

// ---------------------------------------------------------------------------
// Pass 1 (HMMA): g_proj[m][t][b][:] = X[b][t][:] @ Wm_top, bf16-split, 256thr.
// TRANSPOSED TILE ORDER: tile = (t, b0..b0+31) — 32 consecutive b at fixed t.
//  -> epilogue writes into [m][t][B][j] are DENSE (32 rows x 512B contiguous).
//  -> X reads become strided (32 rows 102KB apart) but are only 100MB total
//     and prefetched into registers a full tile ahead (latency hidden).
// Fragment-packed smem compute loop as round 14.
// ---------------------------------------------------------------------------
__global__ __launch_bounds__(256, 1) void proj_kernel(
    const float* __restrict__ x,
    const float* __restrict__ Wu, const float* __restrict__ Wr,
    const float* __restrict__ Wc)
{
    extern __shared__ char smc[];
    char* fB  = smc;                     // [48 g][8 kt][32 lane][16B]
    char* fAh = smc + 196608;            // [2 rt][8 kt][32 lane][16B]
    char* fAl = smc + 204800;
    const int tid  = threadIdx.x;
    const int w    = tid >> 5;
    const int lane = tid & 31;
    const int gr   = lane >> 2;
    const int gc   = lane & 3;
    const int wr   = w >> 2;            // row-group 0..1
    const int wc   = w & 3;             // col-group 0..3 (12 n-tiles each)

    // ---- build fragB from W (top halves), coalesced over j ----
    {
        const float* Ws[3] = {Wu, Wr, Wc};
        for (int idx = tid; idx < 24576; idx += 256) {
            int j  = idx & 127;
            int kp = (idx >> 7) & 63;      // k pair index, k = 2*kp
            int m  = idx >> 13;
            int k  = kp * 2;
            const float* W = Ws[m];
            float h0, h1;
            float l0 = bf16hi_res(W[k * 128 + j], h0);
            float l1 = bf16hi_res(W[(k + 1) * 128 + j], h1);
            int g   = m * 16 + (j >> 3);
            int grr = j & 7;
            int kt  = k >> 4;
            int qcc = (k & 7) >> 1;
            int hi8 = (k & 8) >> 3;        // 0: b0 slot, 1: b1 slot
            char* cell = fB + (((g * 8 + kt) * 32 + grr * 4 + qcc) << 4);
            *(uint32*)(cell + hi8 * 4)     = pk_bf16(h0, h1);   // bh0/bh1
            *(uint32*)(cell + 8 + hi8 * 4) = pk_bf16(l0, l1);   // bl0/bl1
        }
    }

    const float4* x4 = (const float4*)x;
    const int ntiles = (B_ * T_) / 32;     // 6400: tile -> t = tile>>5, b0 = (tile&31)*32

    // Prefetch first tile: thread covers rows r = (tid + c*256)>>5 of the tile.
    float4 xreg[4];
    int tile = blockIdx.x;
    if (tile < ntiles) {
        int t0 = tile >> 5, b0 = (tile & 31) * 32;
#pragma unroll
        for (int c = 0; c < 4; ++c) {
            int f = tid + c * 256;
            int r = f >> 5, kq = f & 31;
            xreg[c] = x4[((size_t)(b0 + r) * T_ + t0) * 32 + kq];
        }
    }

    for (; tile < ntiles; tile += gridDim.x) {
        __syncthreads();   // previous tile's readers done (covers fragB init)
        // ---- stage X into A-fragment layout ----
#pragma unroll
        for (int c = 0; c < 4; ++c) {
            int f = tid + c * 256;
            int r = f >> 5;                // 0..31
            int k0 = (f & 31) * 4;
            float4 v = xreg[c];
            int rt = r >> 4, rr = r & 15;
            int grr = rr & 7;
            int rowslot = rr >> 3;         // 0 -> a0/a2, 1 -> a1/a3
#pragma unroll
            for (int p_ = 0; p_ < 2; ++p_) {
                int kk = k0 + 2 * p_;
                float e = (p_ == 0) ? v.x : v.z;
                float o = (p_ == 0) ? v.y : v.w;
                int kt  = kk >> 4;
                int qcc = (kk & 7) >> 1;
                int fld = rowslot + (((kk & 8) >> 3) << 1);   // 0..3
                uint32 off = (((rt * 8 + kt) * 32 + grr * 4 + qcc) << 4) + fld * 4;
                float hhe, hho;
                float le = bf16hi_res(e, hhe);
                float lo_ = bf16hi_res(o, hho);
                *(uint32*)(fAh + off) = pk_bf16(hhe, hho);
                *(uint32*)(fAl + off) = pk_bf16(le, lo_);
            }
        }
        __syncthreads();   // fragA ready

        int ntile = tile + gridDim.x;
        if (ntile < ntiles) {
            int tn = ntile >> 5, bn = (ntile & 31) * 32;
#pragma unroll
            for (int c = 0; c < 4; ++c) {
                int f = tid + c * 256;
                int r = f >> 5, kq = f & 31;
                xreg[c] = x4[((size_t)(bn + r) * T_ + tn) * 32 + kq];
            }
        }

        float C[12][4];
#pragma unroll
        for (int n = 0; n < 12; ++n)
#pragma unroll
            for (int i = 0; i < 4; ++i) C[n][i] = 0.f;

#pragma unroll
        for (int kt = 0; kt < 8; ++kt) {
            const uint32 aoff = ((wr * 8 + kt) * 32 + lane) << 4;
            uint4 Ah = *(const uint4*)(fAh + aoff);
            uint4 Al = *(const uint4*)(fAl + aoff);
#pragma unroll
            for (int nt = 0; nt < 12; ++nt) {
                int g = wc * 12 + nt;
                uint4 Bf = *(const uint4*)(fB + (((g * 8 + kt) * 32 + lane) << 4));
                mma_bf16(C[nt][0], C[nt][1], C[nt][2], C[nt][3],
                         Ah.x, Ah.y, Ah.z, Ah.w, Bf.x, Bf.y);
                mma_bf16(C[nt][0], C[nt][1], C[nt][2], C[nt][3],
                         Ah.x, Ah.y, Ah.z, Ah.w, Bf.z, Bf.w);
                mma_bf16(C[nt][0], C[nt][1], C[nt][2], C[nt][3],
                         Al.x, Al.y, Al.z, Al.w, Bf.x, Bf.y);
            }
        }

        // ---- epilogue: dense writes (consecutive b at fixed t) ----
        const int tcur = tile >> 5;
        const int bA = (tile & 31) * 32 + wr * 16 + gr;
        const int bB = bA + 8;
#pragma unroll
        for (int nt = 0; nt < 12; ++nt) {
            int cgl = wc * 96 + nt * 8 + gc * 2;
            int m = cgl >> 7, j = cgl & 127;
            float* dA = g_proj + ((size_t)(m * T_ + tcur) * B_ + bA) * 128 + j;
            float* dB = g_proj + ((size_t)(m * T_ + tcur) * B_ + bB) * 128 + j;
            *(float2*)dA = make_float2(C[nt][0], C[nt][1]);
            *(float2*)dB = make_float2(C[nt][2], C[nt][3]);
        }
    }
}

// ---------------------------------------------------------------------------
// Pass 2 (HMMA recurrence): round-12 version verbatim (known-best 382us).
// g_proj layout [m][t][B][j].
// ---------------------------------------------------------------------------
__global__ __launch_bounds__(256, 1) void rec_kernel(
    const float* __restrict__ att,
    const void* __restrict__ slen_raw,
    const float* __restrict__ Wu, const float* __restrict__ Wr,
    const float* __restrict__ Wc,
    float* __restrict__ out)
{
    extern __shared__ char smr[];
    uint32* hfrag = (uint32*)smr;             // [8 kt][32 lane][4 u32]  4096 B
    uint32* sfrag = (uint32*)(smr + 4096);    // [8 kt][32 lane][4 u32]  4096 B
    uint32* blo   = (uint32*)(smr + 8192);    // [48 g][8 kt][32 lane][2 u32] 98304 B
    __shared__ int s_is64;

    const int tid  = threadIdx.x;
    const int w    = tid >> 5;
    const int lane = tid & 31;
    const int qr   = lane >> 2;
    const int qc   = lane & 3;
    const int row  = blockIdx.x * 8 + qr;
    const int colA = w * 16 + qc * 2;
    const int colB = colA + 8;

    uint32 bhi[6][8][2];
#pragma unroll
    for (int f = 0; f < 6; ++f) {
        const float* Wsrc = (f < 2) ? Wu : (f < 4 ? Wr : Wc);
        const int n = w * 16 + (f & 1) * 8 + qr;
#pragma unroll
        for (int kt = 0; kt < 8; ++kt) {
            int k = kt * 16 + qc * 2;
            float h00, h01, h10, h11;
            float l00 = bf16hi_res(Wsrc[16384 + k * 128 + n], h00);
            float l01 = bf16hi_res(Wsrc[16384 + (k + 1) * 128 + n], h01);
            float l10 = bf16hi_res(Wsrc[16384 + (k + 8) * 128 + n], h10);
            float l11 = bf16hi_res(Wsrc[16384 + (k + 9) * 128 + n], h11);
            bhi[f][kt][0] = pk_bf16(h00, h01);
            bhi[f][kt][1] = pk_bf16(h10, h11);
            uint32* dst = blo + (((w * 6 + f) * 8 + kt) * 32 + lane) * 2;
            dst[0] = pk_bf16(l00, l01);
            dst[1] = pk_bf16(l10, l11);
        }
    }
    for (int i = tid; i < 1024; i += 256) hfrag[i] = 0u;
    if (tid == 0) {
        const int* a = (const int*)slen_raw;
        s_is64 = (a[1] == 0 && a[3] == 0 && a[5] == 0 && a[7] == 0) ? 1 : 0;
    }
    __syncthreads();

    int sl;
    if (s_is64) sl = (int)((const long long*)slen_raw)[row];
    else        sl = ((const int*)slen_raw)[row];

    float h0 = 0.f, h1 = 0.f, h2 = 0.f, h3 = 0.f;

    for (int t = 0; t < T_; ++t) {
        float Dg[4][4];
#pragma unroll
        for (int f = 0; f < 4; ++f)
#pragma unroll
            for (int i = 0; i < 4; ++i) Dg[f][i] = 0.f;

#pragma unroll
        for (int kt = 0; kt < 8; ++kt) {
            uint4 af = *(const uint4*)(hfrag + (kt * 32 + lane) * 4);
#pragma unroll
            for (int f = 0; f < 4; ++f) {
                const uint32* bl = blo + (((w * 6 + f) * 8 + kt) * 32 + lane) * 2;
                uint32 bl0 = bl[0], bl1 = bl[1];
                mma_bf16(Dg[f][0], Dg[f][1], Dg[f][2], Dg[f][3],
                         af.x, af.z, af.y, af.w, bhi[f][kt][0], bhi[f][kt][1]);
                mma_bf16(Dg[f][0], Dg[f][1], Dg[f][2], Dg[f][3],
                         af.x, af.z, af.y, af.w, bl0, bl1);
            }
        }

        const float* gp = g_proj + (size_t)t * B_ * 128 + (size_t)row * 128;
        float2 xuA = *(const float2*)(gp + colA);
        float2 xuB = *(const float2*)(gp + colB);
        float2 xrA = *(const float2*)(gp + (size_t)T_ * B_ * 128 + colA);
        float2 xrB = *(const float2*)(gp + (size_t)T_ * B_ * 128 + colB);
        float uA0 = sig_hw(Dg[0][0] + Dg[0][2] + xuA.x);
        float uA1 = sig_hw(Dg[0][1] + Dg[0][3] + xuA.y);
        float uB0 = sig_hw(Dg[1][0] + Dg[1][2] + xuB.x);
        float uB1 = sig_hw(Dg[1][1] + Dg[1][3] + xuB.y);
        float sA0 = sig_hw(Dg[2][0] + Dg[2][2] + xrA.x) * h0;
        float sA1 = sig_hw(Dg[2][1] + Dg[2][3] + xrA.y) * h1;
        float sB0 = sig_hw(Dg[3][0] + Dg[3][2] + xrB.x) * h2;
        float sB1 = sig_hw(Dg[3][1] + Dg[3][3] + xrB.y) * h3;
        {
            float hA0, hA1, hB0, hB1;
            float lA0 = bf16hi_res(sA0, hA0), lA1 = bf16hi_res(sA1, hA1);
            float lB0 = bf16hi_res(sB0, hB0), lB1 = bf16hi_res(sB1, hB1);
            uint4 sf;
            sf.x = pk_bf16(hA0, hA1); sf.y = pk_bf16(hB0, hB1);
            sf.z = pk_bf16(lA0, lA1); sf.w = pk_bf16(lB0, lB1);
            *(uint4*)(sfrag + (w * 32 + lane) * 4) = sf;
        }
        __syncthreads();

        float Dc[2][4];
#pragma unroll
        for (int f = 0; f < 2; ++f)
#pragma unroll
            for (int i = 0; i < 4; ++i) Dc[f][i] = 0.f;

#pragma unroll
        for (int kt = 0; kt < 8; ++kt) {
            uint4 af = *(const uint4*)(sfrag + (kt * 32 + lane) * 4);
#pragma unroll
            for (int f = 0; f < 2; ++f) {
                const uint32* bl = blo + (((w * 6 + 4 + f) * 8 + kt) * 32 + lane) * 2;
                uint32 bl0 = bl[0], bl1 = bl[1];
                mma_bf16(Dc[f][0], Dc[f][1], Dc[f][2], Dc[f][3],
                         af.x, af.z, af.y, af.w, bhi[4 + f][kt][0], bhi[4 + f][kt][1]);
                mma_bf16(Dc[f][0], Dc[f][1], Dc[f][2], Dc[f][3],
                         af.x, af.z, af.y, af.w, bl0, bl1);
            }
        }

        float2 xcA = *(const float2*)(gp + (size_t)2 * T_ * B_ * 128 + colA);
        float2 xcB = *(const float2*)(gp + (size_t)2 * T_ * B_ * 128 + colB);
        float av = att[(size_t)row * T_ + t];
        bool live = (t < sl);
        {
            float htA0 = tanh_hw(Dc[0][0] + Dc[0][2] + xcA.x);
            float htA1 = tanh_hw(Dc[0][1] + Dc[0][3] + xcA.y);
            float htB0 = tanh_hw(Dc[1][0] + Dc[1][2] + xcB.x);
            float htB1 = tanh_hw(Dc[1][1] + Dc[1][3] + xcB.y);
            float n0 = h0 + uA0 * av * (htA0 - h0);
            float n1 = h1 + uA1 * av * (htA1 - h1);
            float n2 = h2 + uB0 * av * (htB0 - h2);
            float n3 = h3 + uB1 * av * (htB1 - h3);
            h0 = live ? n0 : h0;
            h1 = live ? n1 : h1;
            h2 = live ? n2 : h2;
            h3 = live ? n3 : h3;
        }
        float* op = out + ((size_t)row * T_ + t) * 128;
        *(float2*)(op + colA) = make_float2(h0, h1);
        *(float2*)(op + colB) = make_float2(h2, h3);
        {
            float hA0, hA1, hB0, hB1;
            float lA0 = bf16hi_res(h0, hA0), lA1 = bf16hi_res(h1, hA1);
            float lB0 = bf16hi_res(h2, hB0), lB1 = bf16hi_res(h3, hB1);
            uint4 hf;
            hf.x = pk_bf16(hA0, hA1); hf.y = pk_bf16(hB0, hB1);
            hf.z = pk_bf16(lA0, lA1); hf.w = pk_bf16(lB0, lB1);
            *(uint4*)(hfrag + (w * 32 + lane) * 4) = hf;
        }
        __syncthreads();
    }
}

// ---------------------------------------------------------------------------
extern "C" void kernel_launch(void* const* d_in, const int* in_sizes, int n_in,
                              void* d_out, int out_size)
{
    // Resolve inputs by element count (robust to metadata ordering).
    int iSeq = -1, iLen = -1, iAtt = -1, iW[3] = {-1, -1, -1};
    int nw = 0;
    for (int i = 0; i < n_in; ++i) {
        int s = in_sizes[i];
        if      (s == 26214400) iSeq = i;
        else if (s == 1024)     iLen = i;
        else if (s == 204800)   iAtt = i;
        else if (s == 32768 && nw < 3) iW[nw++] = i;
    }
    if (iSeq < 0 || iLen < 0 || iAtt < 0 || nw != 3) {
        iSeq = 0; iLen = 1; iAtt = 2; iW[0] = 3; iW[1] = 4; iW[2] = 5;
    }
    int iWu, iWr, iWc;
    if (iW[0] < iSeq) { iWc = iW[0]; iWr = iW[1]; iWu = iW[2]; }  // alphabetical
    else              { iWu = iW[0]; iWr = iW[1]; iWc = iW[2]; }  // insertion

    const float* seq_emb = (const float*)d_in[iSeq];
    const void*  slen    = d_in[iLen];
    const float* att     = (const float*)d_in[iAtt];
    const float* Wu      = (const float*)d_in[iWu];
    const float* Wr      = (const float*)d_in[iWr];
    const float* Wc      = (const float*)d_in[iWc];
    float*       out     = (float*)d_out;

    const int smem1 = 196608 + 2 * 8192;      // 212992 B
    const int smem2 = 8192 + 98304;           // 106496 B
    cudaFuncSetAttribute(proj_kernel, cudaFuncAttributeMaxDynamicSharedMemorySize, smem1);
    cudaFuncSetAttribute(rec_kernel,  cudaFuncAttributeMaxDynamicSharedMemorySize, smem2);

    proj_kernel<<<148, 256, smem1>>>(seq_emb, Wu, Wr, Wc);
    rec_kernel<<<128, 256, smem2>>>(att, slen, Wu, Wr, Wc, out);
}

// round 17
// speedup vs baseline: 1.0936x; 1.0091x over previous
#include <cuda_runtime.h>
#include <cuda_bf16.h>
#include <cstdint>

#define B_ 1024
#define T_ 200

typedef unsigned long long ull;
typedef unsigned int uint32;

// Scratch for x-projections: [m][t][B][j] fp32 (rec-friendly layout).
__device__ float g_proj[(size_t)3 * T_ * B_ * 128];

// HW tanh (MUFU.TANH, sm_75+; base PTX feature).
__device__ __forceinline__ float tanh_hw(float x) {
    float t; asm("tanh.approx.f32 %0, %1;" : "=f"(t) : "f"(x)); return t;
}
__device__ __forceinline__ float sig_hw(float x) {
    return 0.5f * tanh_hw(0.5f * x) + 0.5f;
}

__device__ __forceinline__ uint32 pk_bf16(float a, float b) {
    return (uint32)__bfloat16_as_ushort(__float2bfloat16(a)) |
           ((uint32)__bfloat16_as_ushort(__float2bfloat16(b)) << 16);
}
__device__ __forceinline__ float bf16hi_res(float v, float& hi) {
    __nv_bfloat16 h = __float2bfloat16(v);
    hi = __bfloat162float(h);
    return v - hi;
}
__device__ __forceinline__ void mma_bf16(float& c0, float& c1, float& c2, float& c3,
                                         uint32 a0, uint32 a1, uint32 a2, uint32 a3,
                                         uint32 b0, uint32 b1) {
    asm volatile(
        "mma.sync.aligned.m16n8k16.row.col.f32.bf16.bf16.f32 "
        "{%0,%1,%2,%3}, {%4,%5,%6,%7}, {%8,%9}, {%0,%1,%2,%3};"
        : "+f"(c0), "+f"(c1), "+f"(c2), "+f"(c3)
        : "r"(a0), "r"(a1), "r"(a2), "r"(a3), "r"(b0), "r"(b1));
}

// ---------------------------------------------------------------------------
// Pass 1 (HMMA): g_proj[m][t][b][:] = X[b][t][:] @ Wm_top, bf16-split, 256thr.
// Transposed tile order (t, b0..b0+31): dense writes into [m][t][B][j].
// COL-DISTINCT WARP MAPPING: warp w owns fragment groups [6w, 6w+6) (48 cols)
// over ALL 32 rows -> each B fragment read exactly once per tile (was twice).
// Per kt: 4 A-LDS.128 + 6 B-LDS.128 (was 2 + 12).
// ---------------------------------------------------------------------------
__global__ __launch_bounds__(256, 1) void proj_kernel(
    const float* __restrict__ x,
    const float* __restrict__ Wu, const float* __restrict__ Wr,
    const float* __restrict__ Wc)
{
    extern __shared__ char smc[];
    char* fB  = smc;                     // [48 g][8 kt][32 lane][16B]
    char* fAh = smc + 196608;            // [2 rt][8 kt][32 lane][16B]
    char* fAl = smc + 204800;
    const int tid  = threadIdx.x;
    const int w    = tid >> 5;
    const int lane = tid & 31;
    const int gr   = lane >> 2;
    const int gc   = lane & 3;

    // ---- build fragB from W (top halves), coalesced over j ----
    {
        const float* Ws[3] = {Wu, Wr, Wc};
        for (int idx = tid; idx < 24576; idx += 256) {
            int j  = idx & 127;
            int kp = (idx >> 7) & 63;      // k pair index, k = 2*kp
            int m  = idx >> 13;
            int k  = kp * 2;
            const float* W = Ws[m];
            float h0, h1;
            float l0 = bf16hi_res(W[k * 128 + j], h0);
            float l1 = bf16hi_res(W[(k + 1) * 128 + j], h1);
            int g   = m * 16 + (j >> 3);
            int grr = j & 7;
            int kt  = k >> 4;
            int qcc = (k & 7) >> 1;
            int hi8 = (k & 8) >> 3;        // 0: b0 slot, 1: b1 slot
            char* cell = fB + (((g * 8 + kt) * 32 + grr * 4 + qcc) << 4);
            *(uint32*)(cell + hi8 * 4)     = pk_bf16(h0, h1);   // bh0/bh1
            *(uint32*)(cell + 8 + hi8 * 4) = pk_bf16(l0, l1);   // bl0/bl1
        }
    }

    const float4* x4 = (const float4*)x;
    const int ntiles = (B_ * T_) / 32;     // 6400: t = tile>>5, b0 = (tile&31)*32

    float4 xreg[4];
    int tile = blockIdx.x;
    if (tile < ntiles) {
        int t0 = tile >> 5, b0 = (tile & 31) * 32;
#pragma unroll
        for (int c = 0; c < 4; ++c) {
            int f = tid + c * 256;
            int r = f >> 5, kq = f & 31;
            xreg[c] = x4[((size_t)(b0 + r) * T_ + t0) * 32 + kq];
        }
    }

    for (; tile < ntiles; tile += gridDim.x) {
        __syncthreads();   // previous tile's readers done (covers fragB init)
        // ---- stage X into A-fragment layout ----
#pragma unroll
        for (int c = 0; c < 4; ++c) {
            int f = tid + c * 256;
            int r = f >> 5;                // 0..31
            int k0 = (f & 31) * 4;
            float4 v = xreg[c];
            int rt = r >> 4, rr = r & 15;
            int grr = rr & 7;
            int rowslot = rr >> 3;         // 0 -> a0/a2, 1 -> a1/a3
#pragma unroll
            for (int p_ = 0; p_ < 2; ++p_) {
                int kk = k0 + 2 * p_;
                float e = (p_ == 0) ? v.x : v.z;
                float o = (p_ == 0) ? v.y : v.w;
                int kt  = kk >> 4;
                int qcc = (kk & 7) >> 1;
                int fld = rowslot + (((kk & 8) >> 3) << 1);   // 0..3
                uint32 off = (((rt * 8 + kt) * 32 + grr * 4 + qcc) << 4) + fld * 4;
                float hhe, hho;
                float le = bf16hi_res(e, hhe);
                float lo_ = bf16hi_res(o, hho);
                *(uint32*)(fAh + off) = pk_bf16(hhe, hho);
                *(uint32*)(fAl + off) = pk_bf16(le, lo_);
            }
        }
        __syncthreads();   // fragA ready

        int ntile = tile + gridDim.x;
        if (ntile < ntiles) {
            int tn = ntile >> 5, bn = (ntile & 31) * 32;
#pragma unroll
            for (int c = 0; c < 4; ++c) {
                int f = tid + c * 256;
                int r = f >> 5, kq = f & 31;
                xreg[c] = x4[((size_t)(bn + r) * T_ + tn) * 32 + kq];
            }
        }

        float C[2][6][4];
#pragma unroll
        for (int rt = 0; rt < 2; ++rt)
#pragma unroll
            for (int n = 0; n < 6; ++n)
#pragma unroll
                for (int i = 0; i < 4; ++i) C[rt][n][i] = 0.f;

#pragma unroll
        for (int kt = 0; kt < 8; ++kt) {
            uint4 Ah[2], Al[2];
#pragma unroll
            for (int rt = 0; rt < 2; ++rt) {
                const uint32 aoff = ((rt * 8 + kt) * 32 + lane) << 4;
                Ah[rt] = *(const uint4*)(fAh + aoff);
                Al[rt] = *(const uint4*)(fAl + aoff);
            }
#pragma unroll
            for (int nt = 0; nt < 6; ++nt) {
                int g = w * 6 + nt;
                uint4 Bf = *(const uint4*)(fB + (((g * 8 + kt) * 32 + lane) << 4));
#pragma unroll
                for (int rt = 0; rt < 2; ++rt) {
                    mma_bf16(C[rt][nt][0], C[rt][nt][1], C[rt][nt][2], C[rt][nt][3],
                             Ah[rt].x, Ah[rt].y, Ah[rt].z, Ah[rt].w, Bf.x, Bf.y);
                    mma_bf16(C[rt][nt][0], C[rt][nt][1], C[rt][nt][2], C[rt][nt][3],
                             Ah[rt].x, Ah[rt].y, Ah[rt].z, Ah[rt].w, Bf.z, Bf.w);
                    mma_bf16(C[rt][nt][0], C[rt][nt][1], C[rt][nt][2], C[rt][nt][3],
                             Al[rt].x, Al[rt].y, Al[rt].z, Al[rt].w, Bf.x, Bf.y);
                }
            }
        }

        // ---- epilogue: dense writes (consecutive b at fixed t) ----
        const int tcur = tile >> 5;
        const int bbase = (tile & 31) * 32;
#pragma unroll
        for (int rt = 0; rt < 2; ++rt) {
            const int bA = bbase + rt * 16 + gr;
            const int bB = bA + 8;
#pragma unroll
            for (int nt = 0; nt < 6; ++nt) {
                int cgl = w * 48 + nt * 8 + gc * 2;
                int m = cgl >> 7, j = cgl & 127;
                float* dA = g_proj + ((size_t)(m * T_ + tcur) * B_ + bA) * 128 + j;
                float* dB = g_proj + ((size_t)(m * T_ + tcur) * B_ + bB) * 128 + j;
                *(float2*)dA = make_float2(C[rt][nt][0], C[rt][nt][1]);
                *(float2*)dB = make_float2(C[rt][nt][2], C[rt][nt][3]);
            }
        }
    }
}

// ---------------------------------------------------------------------------
// Pass 2 (HMMA recurrence): round-12/16 version verbatim (known-best 381us).
// g_proj layout [m][t][B][j].
// ---------------------------------------------------------------------------
__global__ __launch_bounds__(256, 1) void rec_kernel(
    const float* __restrict__ att,
    const void* __restrict__ slen_raw,
    const float* __restrict__ Wu, const float* __restrict__ Wr,
    const float* __restrict__ Wc,
    float* __restrict__ out)
{
    extern __shared__ char smr[];
    uint32* hfrag = (uint32*)smr;             // [8 kt][32 lane][4 u32]  4096 B
    uint32* sfrag = (uint32*)(smr + 4096);    // [8 kt][32 lane][4 u32]  4096 B
    uint32* blo   = (uint32*)(smr + 8192);    // [48 g][8 kt][32 lane][2 u32] 98304 B
    __shared__ int s_is64;

    const int tid  = threadIdx.x;
    const int w    = tid >> 5;
    const int lane = tid & 31;
    const int qr   = lane >> 2;
    const int qc   = lane & 3;
    const int row  = blockIdx.x * 8 + qr;
    const int colA = w * 16 + qc * 2;
    const int colB = colA + 8;

    uint32 bhi[6][8][2];
#pragma unroll
    for (int f = 0; f < 6; ++f) {
        const float* Wsrc = (f < 2) ? Wu : (f < 4 ? Wr : Wc);
        const int n = w * 16 + (f & 1) * 8 + qr;
#pragma unroll
        for (int kt = 0; kt < 8; ++kt) {
            int k = kt * 16 + qc * 2;
            float h00, h01, h10, h11;
            float l00 = bf16hi_res(Wsrc[16384 + k * 128 + n], h00);
            float l01 = bf16hi_res(Wsrc[16384 + (k + 1) * 128 + n], h01);
            float l10 = bf16hi_res(Wsrc[16384 + (k + 8) * 128 + n], h10);
            float l11 = bf16hi_res(Wsrc[16384 + (k + 9) * 128 + n], h11);
            bhi[f][kt][0] = pk_bf16(h00, h01);
            bhi[f][kt][1] = pk_bf16(h10, h11);
            uint32* dst = blo + (((w * 6 + f) * 8 + kt) * 32 + lane) * 2;
            dst[0] = pk_bf16(l00, l01);
            dst[1] = pk_bf16(l10, l11);
        }
    }
    for (int i = tid; i < 1024; i += 256) hfrag[i] = 0u;
    if (tid == 0) {
        const int* a = (const int*)slen_raw;
        s_is64 = (a[1] == 0 && a[3] == 0 && a[5] == 0 && a[7] == 0) ? 1 : 0;
    }
    __syncthreads();

    int sl;
    if (s_is64) sl = (int)((const long long*)slen_raw)[row];
    else        sl = ((const int*)slen_raw)[row];

    float h0 = 0.f, h1 = 0.f, h2 = 0.f, h3 = 0.f;

    for (int t = 0; t < T_; ++t) {
        float Dg[4][4];
#pragma unroll
        for (int f = 0; f < 4; ++f)
#pragma unroll
            for (int i = 0; i < 4; ++i) Dg[f][i] = 0.f;

#pragma unroll
        for (int kt = 0; kt < 8; ++kt) {
            uint4 af = *(const uint4*)(hfrag + (kt * 32 + lane) * 4);
#pragma unroll
            for (int f = 0; f < 4; ++f) {
                const uint32* bl = blo + (((w * 6 + f) * 8 + kt) * 32 + lane) * 2;
                uint32 bl0 = bl[0], bl1 = bl[1];
                mma_bf16(Dg[f][0], Dg[f][1], Dg[f][2], Dg[f][3],
                         af.x, af.z, af.y, af.w, bhi[f][kt][0], bhi[f][kt][1]);
                mma_bf16(Dg[f][0], Dg[f][1], Dg[f][2], Dg[f][3],
                         af.x, af.z, af.y, af.w, bl0, bl1);
            }
        }

        const float* gp = g_proj + (size_t)t * B_ * 128 + (size_t)row * 128;
        float2 xuA = *(const float2*)(gp + colA);
        float2 xuB = *(const float2*)(gp + colB);
        float2 xrA = *(const float2*)(gp + (size_t)T_ * B_ * 128 + colA);
        float2 xrB = *(const float2*)(gp + (size_t)T_ * B_ * 128 + colB);
        float uA0 = sig_hw(Dg[0][0] + Dg[0][2] + xuA.x);
        float uA1 = sig_hw(Dg[0][1] + Dg[0][3] + xuA.y);
        float uB0 = sig_hw(Dg[1][0] + Dg[1][2] + xuB.x);
        float uB1 = sig_hw(Dg[1][1] + Dg[1][3] + xuB.y);
        float sA0 = sig_hw(Dg[2][0] + Dg[2][2] + xrA.x) * h0;
        float sA1 = sig_hw(Dg[2][1] + Dg[2][3] + xrA.y) * h1;
        float sB0 = sig_hw(Dg[3][0] + Dg[3][2] + xrB.x) * h2;
        float sB1 = sig_hw(Dg[3][1] + Dg[3][3] + xrB.y) * h3;
        {
            float hA0, hA1, hB0, hB1;
            float lA0 = bf16hi_res(sA0, hA0), lA1 = bf16hi_res(sA1, hA1);
            float lB0 = bf16hi_res(sB0, hB0), lB1 = bf16hi_res(sB1, hB1);
            uint4 sf;
            sf.x = pk_bf16(hA0, hA1); sf.y = pk_bf16(hB0, hB1);
            sf.z = pk_bf16(lA0, lA1); sf.w = pk_bf16(lB0, lB1);
            *(uint4*)(sfrag + (w * 32 + lane) * 4) = sf;
        }
        __syncthreads();

        float Dc[2][4];
#pragma unroll
        for (int f = 0; f < 2; ++f)
#pragma unroll
            for (int i = 0; i < 4; ++i) Dc[f][i] = 0.f;

#pragma unroll
        for (int kt = 0; kt < 8; ++kt) {
            uint4 af = *(const uint4*)(sfrag + (kt * 32 + lane) * 4);
#pragma unroll
            for (int f = 0; f < 2; ++f) {
                const uint32* bl = blo + (((w * 6 + 4 + f) * 8 + kt) * 32 + lane) * 2;
                uint32 bl0 = bl[0], bl1 = bl[1];
                mma_bf16(Dc[f][0], Dc[f][1], Dc[f][2], Dc[f][3],
                         af.x, af.z, af.y, af.w, bhi[4 + f][kt][0], bhi[4 + f][kt][1]);
                mma_bf16(Dc[f][0], Dc[f][1], Dc[f][2], Dc[f][3],
                         af.x, af.z, af.y, af.w, bl0, bl1);
            }
        }

        float2 xcA = *(const float2*)(gp + (size_t)2 * T_ * B_ * 128 + colA);
        float2 xcB = *(const float2*)(gp + (size_t)2 * T_ * B_ * 128 + colB);
        float av = att[(size_t)row * T_ + t];
        bool live = (t < sl);
        {
            float htA0 = tanh_hw(Dc[0][0] + Dc[0][2] + xcA.x);
            float htA1 = tanh_hw(Dc[0][1] + Dc[0][3] + xcA.y);
            float htB0 = tanh_hw(Dc[1][0] + Dc[1][2] + xcB.x);
            float htB1 = tanh_hw(Dc[1][1] + Dc[1][3] + xcB.y);
            float n0 = h0 + uA0 * av * (htA0 - h0);
            float n1 = h1 + uA1 * av * (htA1 - h1);
            float n2 = h2 + uB0 * av * (htB0 - h2);
            float n3 = h3 + uB1 * av * (htB1 - h3);
            h0 = live ? n0 : h0;
            h1 = live ? n1 : h1;
            h2 = live ? n2 : h2;
            h3 = live ? n3 : h3;
        }
        float* op = out + ((size_t)row * T_ + t) * 128;
        *(float2*)(op + colA) = make_float2(h0, h1);
        *(float2*)(op + colB) = make_float2(h2, h3);
        {
            float hA0, hA1, hB0, hB1;
            float lA0 = bf16hi_res(h0, hA0), lA1 = bf16hi_res(h1, hA1);
            float lB0 = bf16hi_res(h2, hB0), lB1 = bf16hi_res(h3, hB1);
            uint4 hf;
            hf.x = pk_bf16(hA0, hA1); hf.y = pk_bf16(hB0, hB1);
            hf.z = pk_bf16(lA0, lA1); hf.w = pk_bf16(lB0, lB1);
            *(uint4*)(hfrag + (w * 32 + lane) * 4) = hf;
        }
        __syncthreads();
    }
}

// ---------------------------------------------------------------------------
extern "C" void kernel_launch(void* const* d_in, const int* in_sizes, int n_in,
                              void* d_out, int out_size)
{
    // Resolve inputs by element count (robust to metadata ordering).
    int iSeq = -1, iLen = -1, iAtt = -1, iW[3] = {-1, -1, -1};
    int nw = 0;
    for (int i = 0; i < n_in; ++i) {
        int s = in_sizes[i];
        if      (s == 26214400) iSeq = i;
        else if (s == 1024)     iLen = i;
        else if (s == 204800)   iAtt = i;
        else if (s == 32768 && nw < 3) iW[nw++] = i;
    }
    if (iSeq < 0 || iLen < 0 || iAtt < 0 || nw != 3) {
        iSeq = 0; iLen = 1; iAtt = 2; iW[0] = 3; iW[1] = 4; iW[2] = 5;
    }
    int iWu, iWr, iWc;
    if (iW[0] < iSeq) { iWc = iW[0]; iWr = iW[1]; iWu = iW[2]; }  // alphabetical
    else              { iWu = iW[0]; iWr = iW[1]; iWc = iW[2]; }  // insertion

    const float* seq_emb = (const float*)d_in[iSeq];
    const void*  slen    = d_in[iLen];
    const float* att     = (const float*)d_in[iAtt];
    const float* Wu      = (const float*)d_in[iWu];
    const float* Wr      = (const float*)d_in[iWr];
    const float* Wc      = (const float*)d_in[iWc];
    float*       out     = (float*)d_out;

    const int smem1 = 196608 + 2 * 8192;      // 212992 B
    const int smem2 = 8192 + 98304;           // 106496 B
    cudaFuncSetAttribute(proj_kernel, cudaFuncAttributeMaxDynamicSharedMemorySize, smem1);
    cudaFuncSetAttribute(rec_kernel,  cudaFuncAttributeMaxDynamicSharedMemorySize, smem2);

    proj_kernel<<<148, 256, smem1>>>(seq_emb, Wu, Wr, Wc);
    rec_kernel<<<128, 256, smem2>>>(att, slen, Wu, Wr, Wc, out);
}